// round 7
// baseline (speedup 1.0000x reference)
#include <cuda_runtime.h>
#include <math.h>
#include <stdint.h>

#define BTN 4096          // B*T
#define HN 256            // hidden
#define NPIM 4096

// ------------------ scratch (device globals; no allocation allowed) ------------------
__device__ float  g_F[BTN * 256];          // conv features
__device__ float  g_G[BTN * 1024];         // x@Wk + b (gate x-parts)
__device__ float  g_HS[BTN * 256];         // all lstm hidden states, row=(b*64+t)
__device__ float  g_WrT[1024 * 256];       // Wr transposed: [(u*4+gate)][k]
__device__ float  g_L[(size_t)BTN * NPIM]; // pim logits (64MB)
__device__ float  g_P[BTN];                // chosen-action prob per row
__device__ float  g_V[BTN];                // vpred (incl bias)
__device__ double g_acc[2];                // [0]=entropy sum, [1]=vf sum
__device__ unsigned g_bar_cnt;             // grid barrier counter
__device__ unsigned g_bar_gen;             // grid barrier generation

__device__ __forceinline__ float lrelu(float v) { return v > 0.f ? v : 0.2f * v; }
__device__ __forceinline__ float sigm(float v)  { return 1.f / (1.f + expf(-v)); }

// ------------------ init ------------------
__global__ void init_kernel() {
    int i = blockIdx.x * 256 + threadIdx.x;
    if (i < 2) g_acc[i] = 0.0;
    if (i == 2) { g_bar_cnt = 0u; g_bar_gen = 0u; }
}

// ------------------ fused conv stack: one sample per block, 128 threads ------------------
__global__ void __launch_bounds__(128) conv_kernel(
    const float* __restrict__ X,
    const float* __restrict__ W1, const float* __restrict__ b1,
    const float* __restrict__ W2, const float* __restrict__ b2,
    const float* __restrict__ W3, const float* __restrict__ b3,
    const float* __restrict__ W4, const float* __restrict__ b4)
{
    __shared__ float xin[832];   // 13x8x8
    __shared__ float a1[384];    // 6x4x16
    __shared__ float a2[480];    // 5x3x32
    __shared__ float a3[128];    // 2x1x64
    int s = blockIdx.x, tid = threadIdx.x;

    for (int i = tid; i < 832; i += 128) xin[i] = X[(size_t)s * 832 + i];
    __syncthreads();

    // conv1: 2x2 s2 -> (6,4,16)
    if (tid < 96) {
        int cg = tid & 3, xo = (tid >> 2) & 3, yo = tid >> 4;
        float4 acc = *reinterpret_cast<const float4*>(b1 + cg * 4);
        #pragma unroll
        for (int ky = 0; ky < 2; ky++)
        #pragma unroll
        for (int kx = 0; kx < 2; kx++)
        #pragma unroll
        for (int ci = 0; ci < 8; ci++) {
            float v = xin[((2 * yo + ky) * 8 + 2 * xo + kx) * 8 + ci];
            float4 w = *reinterpret_cast<const float4*>(W1 + ((ky * 2 + kx) * 8 + ci) * 16 + cg * 4);
            acc.x = fmaf(v, w.x, acc.x); acc.y = fmaf(v, w.y, acc.y);
            acc.z = fmaf(v, w.z, acc.z); acc.w = fmaf(v, w.w, acc.w);
        }
        int base = (yo * 4 + xo) * 16 + cg * 4;
        a1[base + 0] = lrelu(acc.x); a1[base + 1] = lrelu(acc.y);
        a1[base + 2] = lrelu(acc.z); a1[base + 3] = lrelu(acc.w);
    }
    __syncthreads();

    // conv2: 2x2 s1 -> (5,3,32)
    if (tid < 120) {
        int cg = tid & 7, xo = (tid >> 3) % 3, yo = tid / 24;
        float4 acc = *reinterpret_cast<const float4*>(b2 + cg * 4);
        #pragma unroll
        for (int ky = 0; ky < 2; ky++)
        #pragma unroll
        for (int kx = 0; kx < 2; kx++)
        #pragma unroll
        for (int ci = 0; ci < 16; ci++) {
            float v = a1[((yo + ky) * 4 + xo + kx) * 16 + ci];
            float4 w = *reinterpret_cast<const float4*>(W2 + ((ky * 2 + kx) * 16 + ci) * 32 + cg * 4);
            acc.x = fmaf(v, w.x, acc.x); acc.y = fmaf(v, w.y, acc.y);
            acc.z = fmaf(v, w.z, acc.z); acc.w = fmaf(v, w.w, acc.w);
        }
        int base = (yo * 3 + xo) * 32 + cg * 4;
        a2[base + 0] = lrelu(acc.x); a2[base + 1] = lrelu(acc.y);
        a2[base + 2] = lrelu(acc.z); a2[base + 3] = lrelu(acc.w);
    }
    __syncthreads();

    // conv3: 2x2 s2 -> (2,1,64)
    {
        int yo = tid >> 6, co = tid & 63;
        float acc = b3[co];
        #pragma unroll
        for (int ky = 0; ky < 2; ky++)
        #pragma unroll
        for (int kx = 0; kx < 2; kx++)
        for (int ci = 0; ci < 32; ci++) {
            acc = fmaf(a2[((2 * yo + ky) * 3 + kx) * 32 + ci],
                       W3[((ky * 2 + kx) * 32 + ci) * 64 + co], acc);
        }
        a3[yo * 64 + co] = lrelu(acc);
    }
    __syncthreads();

    // conv4: 1x1 -> (2,1,128); feature j = co*2 + y (keras channels_first flatten)
    #pragma unroll
    for (int rep = 0; rep < 2; rep++) {
        int idx = tid + rep * 128;
        int yo = idx >> 7, co = idx & 127;
        float acc = b4[co];
        for (int ci = 0; ci < 64; ci++)
            acc = fmaf(a3[yo * 64 + ci], W4[ci * 128 + co], acc);
        g_F[(size_t)s * 256 + co * 2 + yo] = lrelu(acc);
    }
}

// ------------------ tiled fp32 GEMM with register-prefetch double buffering ------------------
// C[MxN] = A[MxK] @ W[KxN] + bias. BM=BN=128, BK=8, 256 threads, 8x8 per thread.
__global__ void __launch_bounds__(256) gemm_bias(
    const float* __restrict__ A, const float* __restrict__ W,
    const float* __restrict__ bias, float* __restrict__ C,
    int M, int N, int K)
{
    __shared__ float As[8][128];
    __shared__ float Ws[8][128];
    int m0 = blockIdx.y * 128, n0 = blockIdx.x * 128;
    int tid = threadIdx.x;
    int tx = tid & 15, ty = tid >> 4;
    int lm = tid >> 1, lkq = (tid & 1) * 4;   // A loader
    int lk = tid >> 5, lj = (tid & 31) * 4;   // W loader

    const float* Aptr = A + (size_t)(m0 + lm) * K + lkq;
    const float* Wptr = W + (size_t)lk * N + n0 + lj;

    float acc[8][8];
    #pragma unroll
    for (int i = 0; i < 8; i++)
        #pragma unroll
        for (int j = 0; j < 8; j++) acc[i][j] = 0.f;

    float4 av = *reinterpret_cast<const float4*>(Aptr);
    float4 wv = *reinterpret_cast<const float4*>(Wptr);

    for (int k0 = 0; k0 < K; k0 += 8) {
        As[lkq + 0][lm] = av.x; As[lkq + 1][lm] = av.y;
        As[lkq + 2][lm] = av.z; As[lkq + 3][lm] = av.w;
        *reinterpret_cast<float4*>(&Ws[lk][lj]) = wv;
        __syncthreads();

        if (k0 + 8 < K) {   // prefetch next tile while computing this one
            av = *reinterpret_cast<const float4*>(Aptr + k0 + 8);
            wv = *reinterpret_cast<const float4*>(Wptr + (size_t)(k0 + 8) * N);
        }

        #pragma unroll
        for (int kk = 0; kk < 8; kk++) {
            float4 a0 = *reinterpret_cast<float4*>(&As[kk][ty * 4]);
            float4 a1 = *reinterpret_cast<float4*>(&As[kk][64 + ty * 4]);
            float4 b0 = *reinterpret_cast<float4*>(&Ws[kk][tx * 4]);
            float4 b1 = *reinterpret_cast<float4*>(&Ws[kk][64 + tx * 4]);
            float ar[8] = {a0.x, a0.y, a0.z, a0.w, a1.x, a1.y, a1.z, a1.w};
            float br[8] = {b0.x, b0.y, b0.z, b0.w, b1.x, b1.y, b1.z, b1.w};
            #pragma unroll
            for (int i = 0; i < 8; i++)
                #pragma unroll
                for (int j = 0; j < 8; j++)
                    acc[i][j] = fmaf(ar[i], br[j], acc[i][j]);
        }
        __syncthreads();
    }
    #pragma unroll
    for (int i2 = 0; i2 < 2; i2++)
    #pragma unroll
    for (int i = 0; i < 4; i++) {
        int m = m0 + i2 * 64 + ty * 4 + i;
        #pragma unroll
        for (int j2 = 0; j2 < 2; j2++) {
            int n = n0 + j2 * 64 + tx * 4;
            float4 bv = *reinterpret_cast<const float4*>(bias + n);
            float4 o;
            o.x = acc[i2 * 4 + i][j2 * 4 + 0] + bv.x;
            o.y = acc[i2 * 4 + i][j2 * 4 + 1] + bv.y;
            o.z = acc[i2 * 4 + i][j2 * 4 + 2] + bv.z;
            o.w = acc[i2 * 4 + i][j2 * 4 + 3] + bv.w;
            *reinterpret_cast<float4*>(C + (size_t)m * N + n) = o;
        }
    }
}

// ------------------ Wr transpose: WrT[(u*4+g)][k] = Wr[k][g*256+u] ------------------
__global__ void transpose_wr(const float* __restrict__ Wr) {
    int col = blockIdx.x, k = threadIdx.x;
    int u = col & 255, g = col >> 8;
    g_WrT[(u * 4 + g) * 256 + k] = Wr[k * 1024 + col];
}

// ------------------ persistent LSTM: 128 blocks x 128 threads, 2 units/block ------------------
// All 64 timesteps in one launch. Weights in smem for the whole run; cell state in
// registers; h exchanged through g_HS with a software grid barrier (all 128 blocks
// co-resident: 128 <= 148 SMs, tiny smem/regs).
__global__ void __launch_bounds__(128) lstm_persistent() {
    __shared__ float ws[8][264];   // row = g*2 + usel; 264: 16B-aligned rows, pair stride 8 banks
    int tid = threadIdx.x;
    int usel = tid & 1, b = tid >> 1;
    int u0 = blockIdx.x * 2;
    int u = u0 + usel;

    // load this block's 8 weight rows (2 units x 4 gates x 256) once
    for (int i = tid; i < 2048; i += 128) {
        int row = i >> 8, k = i & 255;
        int uu = row >> 2, g = row & 3;
        ws[g * 2 + uu][k] = g_WrT[((u0 + uu) * 4 + g) * 256 + k];
    }
    __syncthreads();

    const float4* w0 = reinterpret_cast<const float4*>(&ws[0 * 2 + usel][0]);
    const float4* w1 = reinterpret_cast<const float4*>(&ws[1 * 2 + usel][0]);
    const float4* w2 = reinterpret_cast<const float4*>(&ws[2 * 2 + usel][0]);
    const float4* w3 = reinterpret_cast<const float4*>(&ws[3 * 2 + usel][0]);

    float c = 0.f;
    unsigned gen = 0;

    for (int t = 0; t < 64; t++) {
        size_t grow = (size_t)(b * 64 + t) * 1024 + u;
        float a0 = g_G[grow + 0];
        float a1 = g_G[grow + 256];
        float a2 = g_G[grow + 512];
        float a3 = g_G[grow + 768];
        if (t > 0) {
            const float4* h4 = reinterpret_cast<const float4*>(g_HS + (size_t)(b * 64 + t - 1) * 256);
            #pragma unroll 4
            for (int k4 = 0; k4 < 64; k4++) {
                float4 hv = __ldcg(h4 + k4);      // L2-only: skip L1 staleness questions
                float4 v0 = w0[k4], v1 = w1[k4], v2 = w2[k4], v3 = w3[k4];
                a0 += hv.x * v0.x + hv.y * v0.y + hv.z * v0.z + hv.w * v0.w;
                a1 += hv.x * v1.x + hv.y * v1.y + hv.z * v1.z + hv.w * v1.w;
                a2 += hv.x * v2.x + hv.y * v2.y + hv.z * v2.z + hv.w * v2.w;
                a3 += hv.x * v3.x + hv.y * v3.y + hv.z * v3.z + hv.w * v3.w;
            }
        }
        float cn = sigm(a1) * c + sigm(a0) * tanhf(a2);
        float hn = sigm(a3) * tanhf(cn);
        c = cn;
        g_HS[(size_t)(b * 64 + t) * 256 + u] = hn;

        if (t < 63) {
            __threadfence();          // release: h store visible before arrival
            __syncthreads();
            if (tid == 0) {
                unsigned target = gen + 1;
                if (atomicAdd(&g_bar_cnt, 1u) == 127u) {
                    atomicExch(&g_bar_cnt, 0u);       // reset BEFORE release
                    atomicExch(&g_bar_gen, target);   // release
                } else {
                    while (atomicAdd(&g_bar_gen, 0u) < target) __nanosleep(32);
                }
            }
            gen++;
            __syncthreads();
        }
    }
}

// ------------------ small heads: pir softmax/entropy + vpred (one block/row) ------------------
__global__ void __launch_bounds__(64) heads_kernel(
    const float* __restrict__ pir_W, const float* __restrict__ pir_b,
    const float* __restrict__ v_W,   const float* __restrict__ v_b,
    const int* __restrict__ a_taken)
{
    __shared__ float hrow[256];
    __shared__ float lg[40];
    int r = blockIdx.x, tid = threadIdx.x;
    reinterpret_cast<float4*>(hrow)[tid] =
        reinterpret_cast<const float4*>(g_HS + (size_t)r * 256)[tid];
    __syncthreads();
    if (tid < 36) {
        float acc = pir_b[tid];
        for (int k = 0; k < 256; k++) acc = fmaf(hrow[k], pir_W[k * 36 + tid], acc);
        lg[tid] = acc;
    } else if (tid == 36) {
        float acc = v_b[0];
        for (int k = 0; k < 256; k++) acc = fmaf(hrow[k], v_W[k], acc);
        g_V[r] = acc;
    }
    __syncthreads();
    if (tid == 0) {
        float mx = -1e30f;
        for (int j = 0; j < 36; j++) mx = fmaxf(mx, lg[j]);
        float den = 0.f, s2 = 0.f;
        for (int j = 0; j < 36; j++) {
            float l = lg[j] - mx;
            float e = expf(l);
            den += e; s2 += e * l;
        }
        double ent = log((double)den) - (double)s2 / (double)den;  // -sum p log p
        atomicAdd(&g_acc[0], ent);
        if ((r & 1) == 0) {
            int a = a_taken[r];
            g_P[r] = expf(lg[a] - mx) / den;
        }
    }
}

// ------------------ pim: masked softmax + entropy, one block/row over logits ------------------
__global__ void __launch_bounds__(256) pim_kernel(
    const int* __restrict__ mask, const int* __restrict__ a_taken)
{
    __shared__ float red[256];
    __shared__ float red2[256];
    int r = blockIdx.x, tid = threadIdx.x;
    const float* __restrict__ L = g_L + (size_t)r * NPIM;
    const int* __restrict__ mr = mask + (size_t)r * NPIM;

    // pass 1: full-row max (matches jax softmax stabilization; shift cancels)
    float mx = -1e30f;
    for (int j = tid; j < NPIM; j += 256) mx = fmaxf(mx, L[j]);
    red[tid] = mx; __syncthreads();
    for (int s = 128; s > 0; s >>= 1) {
        if (tid < s) red[tid] = fmaxf(red[tid], red[tid + s]);
        __syncthreads();
    }
    mx = red[0]; __syncthreads();

    // pass 2: s1 = sum e*m, s2 = sum e*m*(l-mx)
    float s1 = 0.f, s2 = 0.f;
    for (int j = tid; j < NPIM; j += 256) {
        float l = L[j] - mx;
        float e = mr[j] ? __expf(l) : 0.f;
        s1 += e; s2 += e * l;
    }
    red[tid] = s1; red2[tid] = s2; __syncthreads();
    for (int s = 128; s > 0; s >>= 1) {
        if (tid < s) { red[tid] += red[tid + s]; red2[tid] += red2[tid + s]; }
        __syncthreads();
    }
    if (tid == 0) {
        float den = red[0];
        // -sum_{m=1} q log q ; masked-out entries (pim_e=1) contribute 0
        double ent = log((double)den) - (double)red2[0] / (double)den;
        atomicAdd(&g_acc[0], ent);
        if (r & 1) {
            int a = a_taken[r];                 // taken action always masked-in
            g_P[r] = __expf(L[a] - mx) / den;
        }
    }
}

// ------------------ vf: faithful (BT,BT) broadcast, one block/row-i ------------------
__global__ void __launch_bounds__(256) vf_kernel(
    const float* __restrict__ ovp, const float* __restrict__ ret)
{
    __shared__ float red[256];
    int i = blockIdx.x, tid = threadIdx.x;
    float v = g_V[i];
    float s = 0.f;
    for (int j = tid; j < BTN; j += 256) {
        float o = ovp[j], rr = ret[j];
        float d = v - o;
        float dc = fminf(fmaxf(d, -0.2f), 0.2f);
        float vpc = o + dc;
        float f1 = (v - rr) * (v - rr);
        float f2 = (vpc - rr) * (vpc - rr);
        s += fmaxf(f1, f2);
    }
    red[tid] = s; __syncthreads();
    for (int st = 128; st > 0; st >>= 1) {
        if (tid < st) red[tid] += red[tid + st];
        __syncthreads();
    }
    if (tid == 0) atomicAdd(&g_acc[1], (double)red[0]);
}

// ------------------ final: gae normalize, pg loss, assemble output ------------------
__global__ void __launch_bounds__(512) final_kernel(
    const float* __restrict__ GAE, const float* __restrict__ lg_old,
    float* __restrict__ out)
{
    __shared__ double rs[512];
    __shared__ double rs2[512];
    __shared__ float stats[2];   // mean, denom
    int tid = threadIdx.x;
    double s = 0.0, ss = 0.0;
    for (int t = tid; t < BTN; t += 512) {
        double g = (double)GAE[t];
        s += g; ss += g * g;
    }
    rs[tid] = s; rs2[tid] = ss; __syncthreads();
    for (int st = 256; st > 0; st >>= 1) {
        if (tid < st) { rs[tid] += rs[tid + st]; rs2[tid] += rs2[tid + st]; }
        __syncthreads();
    }
    if (tid == 0) {
        double mean = rs[0] / BTN;
        double var = rs2[0] / BTN - mean * mean;
        if (var < 0.0) var = 0.0;
        stats[0] = (float)mean;
        stats[1] = (float)(sqrt(var) + 1e-8);
    }
    __syncthreads();
    float mean = stats[0], denom = stats[1];
    double pg = 0.0;
    for (int t = tid; t < BTN; t += 512) {
        float g = (GAE[t] - mean) / denom;
        float p = g_P[t];
        float lgn = logf(p);
        float rt = expf(lgn - lg_old[t]);
        float rtc = fminf(fmaxf(rt, 0.8f), 1.2f);
        float pg1 = -g * rt;
        float pg2 = -g * rtc;
        pg += (double)fmaxf(pg1, pg2);
    }
    rs[tid] = pg; __syncthreads();
    for (int st = 256; st > 0; st >>= 1) {
        if (tid < st) rs[tid] += rs[tid + st];
        __syncthreads();
    }
    if (tid == 0) {
        double pg_loss = rs[0] / BTN;
        double entropy = g_acc[0];
        double vf = 0.5 * g_acc[1] / ((double)BTN * (double)BTN);
        out[0] = (float)(pg_loss - entropy + vf);
        out[1] = (float)pg_loss;
        out[2] = (float)entropy;
        out[3] = (float)vf;
    }
}

// ------------------ launch ------------------
extern "C" void kernel_launch(void* const* d_in, const int* in_sizes, int n_in,
                              void* d_out, int out_size) {
    const float* x       = (const float*)d_in[0];
    const int*   mask    = (const int*)  d_in[1];
    const float* lg_old  = (const float*)d_in[2];
    const int*   a_taken = (const int*)  d_in[3];
    const float* GAE     = (const float*)d_in[4];
    const float* ovp     = (const float*)d_in[5];
    const float* ret     = (const float*)d_in[6];
    const float* W1 = (const float*)d_in[7];
    const float* b1 = (const float*)d_in[8];
    const float* W2 = (const float*)d_in[9];
    const float* b2 = (const float*)d_in[10];
    const float* W3 = (const float*)d_in[11];
    const float* b3 = (const float*)d_in[12];
    const float* W4 = (const float*)d_in[13];
    const float* b4 = (const float*)d_in[14];
    const float* lstm_k = (const float*)d_in[15];
    const float* lstm_r = (const float*)d_in[16];
    const float* lstm_b = (const float*)d_in[17];
    const float* pir_W  = (const float*)d_in[18];
    const float* pir_b  = (const float*)d_in[19];
    const float* pim_W  = (const float*)d_in[20];
    const float* pim_b  = (const float*)d_in[21];
    const float* v_W    = (const float*)d_in[22];
    const float* v_b    = (const float*)d_in[23];
    float* out = (float*)d_out;

    float *pF, *pG, *pHS, *pL;
    cudaGetSymbolAddress((void**)&pF,  g_F);
    cudaGetSymbolAddress((void**)&pG,  g_G);
    cudaGetSymbolAddress((void**)&pHS, g_HS);
    cudaGetSymbolAddress((void**)&pL,  g_L);

    init_kernel<<<1, 256>>>();
    conv_kernel<<<BTN, 128>>>(x, W1, b1, W2, b2, W3, b3, W4, b4);
    transpose_wr<<<1024, 256>>>(lstm_r);

    // G = F @ lstm_k + lstm_b   (4096 x 1024 x 256)
    {
        dim3 grid(1024 / 128, BTN / 128);
        gemm_bias<<<grid, 256>>>(pF, lstm_k, lstm_b, pG, BTN, 1024, 256);
    }

    // all 64 timesteps in one persistent launch
    lstm_persistent<<<128, 128>>>();

    // pim logits = HS @ pim_W + pim_b   (4096 x 4096 x 256)
    {
        dim3 grid(NPIM / 128, BTN / 128);
        gemm_bias<<<grid, 256>>>(pHS, pim_W, pim_b, pL, BTN, NPIM, 256);
    }
    heads_kernel<<<BTN, 64>>>(pir_W, pir_b, v_W, v_b, a_taken);
    pim_kernel<<<BTN, 256>>>(mask, a_taken);
    vf_kernel<<<BTN, 256>>>(ovp, ret);
    final_kernel<<<1, 512>>>(GAE, lg_old, out);
}

// round 9
// speedup vs baseline: 1.2977x; 1.2977x over previous
#include <cuda_runtime.h>
#include <math.h>
#include <stdint.h>

#define BTN 4096          // B*T
#define HN 256            // hidden
#define NPIM 4096

// ------------------ scratch (device globals; no allocation allowed) ------------------
__device__ float  g_F[BTN * 256];          // conv features
__device__ float  g_G[BTN * 1024];         // x@Wk + b (gate x-parts)
__device__ float  g_HS[BTN * 256];         // all lstm hidden states, row=(b*64+t)
__device__ float  g_Hb[2][64 * 256];       // compact double-buffered h (L2-hot)
__device__ float  g_WrT[1024 * 256];       // Wr transposed: [(u*4+gate)][k]
__device__ float  g_L[(size_t)BTN * NPIM]; // pim logits (64MB)
__device__ float  g_P[BTN];                // chosen-action prob per row
__device__ float  g_V[BTN];                // vpred (incl bias)
__device__ double g_acc[2];                // [0]=entropy sum, [1]=vf sum
__device__ unsigned g_bar_cnt;             // grid barrier counter
__device__ unsigned g_bar_gen;             // grid barrier generation

__device__ __forceinline__ float lrelu(float v) { return v > 0.f ? v : 0.2f * v; }
__device__ __forceinline__ float sigm(float v)  { return 1.f / (1.f + expf(-v)); }

// ------------------ init ------------------
__global__ void init_kernel() {
    int i = blockIdx.x * 256 + threadIdx.x;
    if (i < 2) g_acc[i] = 0.0;
    if (i == 2) { g_bar_cnt = 0u; g_bar_gen = 0u; }
}

// ------------------ fused conv stack: one sample per block, 128 threads ------------------
__global__ void __launch_bounds__(128) conv_kernel(
    const float* __restrict__ X,
    const float* __restrict__ W1, const float* __restrict__ b1,
    const float* __restrict__ W2, const float* __restrict__ b2,
    const float* __restrict__ W3, const float* __restrict__ b3,
    const float* __restrict__ W4, const float* __restrict__ b4)
{
    __shared__ float xin[832];   // 13x8x8
    __shared__ float a1[384];    // 6x4x16
    __shared__ float a2[480];    // 5x3x32
    __shared__ float a3[128];    // 2x1x64
    int s = blockIdx.x, tid = threadIdx.x;

    for (int i = tid; i < 832; i += 128) xin[i] = X[(size_t)s * 832 + i];
    __syncthreads();

    // conv1: 2x2 s2 -> (6,4,16)
    if (tid < 96) {
        int cg = tid & 3, xo = (tid >> 2) & 3, yo = tid >> 4;
        float4 acc = *reinterpret_cast<const float4*>(b1 + cg * 4);
        #pragma unroll
        for (int ky = 0; ky < 2; ky++)
        #pragma unroll
        for (int kx = 0; kx < 2; kx++)
        #pragma unroll
        for (int ci = 0; ci < 8; ci++) {
            float v = xin[((2 * yo + ky) * 8 + 2 * xo + kx) * 8 + ci];
            float4 w = *reinterpret_cast<const float4*>(W1 + ((ky * 2 + kx) * 8 + ci) * 16 + cg * 4);
            acc.x = fmaf(v, w.x, acc.x); acc.y = fmaf(v, w.y, acc.y);
            acc.z = fmaf(v, w.z, acc.z); acc.w = fmaf(v, w.w, acc.w);
        }
        int base = (yo * 4 + xo) * 16 + cg * 4;
        a1[base + 0] = lrelu(acc.x); a1[base + 1] = lrelu(acc.y);
        a1[base + 2] = lrelu(acc.z); a1[base + 3] = lrelu(acc.w);
    }
    __syncthreads();

    // conv2: 2x2 s1 -> (5,3,32)
    if (tid < 120) {
        int cg = tid & 7, xo = (tid >> 3) % 3, yo = tid / 24;
        float4 acc = *reinterpret_cast<const float4*>(b2 + cg * 4);
        #pragma unroll
        for (int ky = 0; ky < 2; ky++)
        #pragma unroll
        for (int kx = 0; kx < 2; kx++)
        #pragma unroll
        for (int ci = 0; ci < 16; ci++) {
            float v = a1[((yo + ky) * 4 + xo + kx) * 16 + ci];
            float4 w = *reinterpret_cast<const float4*>(W2 + ((ky * 2 + kx) * 16 + ci) * 32 + cg * 4);
            acc.x = fmaf(v, w.x, acc.x); acc.y = fmaf(v, w.y, acc.y);
            acc.z = fmaf(v, w.z, acc.z); acc.w = fmaf(v, w.w, acc.w);
        }
        int base = (yo * 3 + xo) * 32 + cg * 4;
        a2[base + 0] = lrelu(acc.x); a2[base + 1] = lrelu(acc.y);
        a2[base + 2] = lrelu(acc.z); a2[base + 3] = lrelu(acc.w);
    }
    __syncthreads();

    // conv3: 2x2 s2 -> (2,1,64)
    {
        int yo = tid >> 6, co = tid & 63;
        float acc = b3[co];
        #pragma unroll
        for (int ky = 0; ky < 2; ky++)
        #pragma unroll
        for (int kx = 0; kx < 2; kx++)
        for (int ci = 0; ci < 32; ci++) {
            acc = fmaf(a2[((2 * yo + ky) * 3 + kx) * 32 + ci],
                       W3[((ky * 2 + kx) * 32 + ci) * 64 + co], acc);
        }
        a3[yo * 64 + co] = lrelu(acc);
    }
    __syncthreads();

    // conv4: 1x1 -> (2,1,128); feature j = co*2 + y (keras channels_first flatten)
    #pragma unroll
    for (int rep = 0; rep < 2; rep++) {
        int idx = tid + rep * 128;
        int yo = idx >> 7, co = idx & 127;
        float acc = b4[co];
        for (int ci = 0; ci < 64; ci++)
            acc = fmaf(a3[yo * 64 + ci], W4[ci * 128 + co], acc);
        g_F[(size_t)s * 256 + co * 2 + yo] = lrelu(acc);
    }
}

// ------------------ tiled fp32 GEMM with register-prefetch double buffering ------------------
// C[MxN] = A[MxK] @ W[KxN] + bias. BM=BN=128, BK=8, 256 threads, 8x8 per thread.
__global__ void __launch_bounds__(256, 2) gemm_bias(
    const float* __restrict__ A, const float* __restrict__ W,
    const float* __restrict__ bias, float* __restrict__ C,
    int M, int N, int K)
{
    __shared__ float As[8][128];
    __shared__ float Ws[8][128];
    int m0 = blockIdx.y * 128, n0 = blockIdx.x * 128;
    int tid = threadIdx.x;
    int tx = tid & 15, ty = tid >> 4;
    int lm = tid >> 1, lkq = (tid & 1) * 4;   // A loader
    int lk = tid >> 5, lj = (tid & 31) * 4;   // W loader

    const float* Aptr = A + (size_t)(m0 + lm) * K + lkq;
    const float* Wptr = W + (size_t)lk * N + n0 + lj;

    float acc[8][8];
    #pragma unroll
    for (int i = 0; i < 8; i++)
        #pragma unroll
        for (int j = 0; j < 8; j++) acc[i][j] = 0.f;

    float4 av = *reinterpret_cast<const float4*>(Aptr);
    float4 wv = *reinterpret_cast<const float4*>(Wptr);

    for (int k0 = 0; k0 < K; k0 += 8) {
        As[lkq + 0][lm] = av.x; As[lkq + 1][lm] = av.y;
        As[lkq + 2][lm] = av.z; As[lkq + 3][lm] = av.w;
        *reinterpret_cast<float4*>(&Ws[lk][lj]) = wv;
        __syncthreads();

        if (k0 + 8 < K) {   // prefetch next tile while computing this one
            av = *reinterpret_cast<const float4*>(Aptr + k0 + 8);
            wv = *reinterpret_cast<const float4*>(Wptr + (size_t)(k0 + 8) * N);
        }

        #pragma unroll
        for (int kk = 0; kk < 8; kk++) {
            float4 a0 = *reinterpret_cast<float4*>(&As[kk][ty * 4]);
            float4 a1 = *reinterpret_cast<float4*>(&As[kk][64 + ty * 4]);
            float4 b0 = *reinterpret_cast<float4*>(&Ws[kk][tx * 4]);
            float4 b1 = *reinterpret_cast<float4*>(&Ws[kk][64 + tx * 4]);
            float ar[8] = {a0.x, a0.y, a0.z, a0.w, a1.x, a1.y, a1.z, a1.w};
            float br[8] = {b0.x, b0.y, b0.z, b0.w, b1.x, b1.y, b1.z, b1.w};
            #pragma unroll
            for (int i = 0; i < 8; i++)
                #pragma unroll
                for (int j = 0; j < 8; j++)
                    acc[i][j] = fmaf(ar[i], br[j], acc[i][j]);
        }
        __syncthreads();
    }
    #pragma unroll
    for (int i2 = 0; i2 < 2; i2++)
    #pragma unroll
    for (int i = 0; i < 4; i++) {
        int m = m0 + i2 * 64 + ty * 4 + i;
        #pragma unroll
        for (int j2 = 0; j2 < 2; j2++) {
            int n = n0 + j2 * 64 + tx * 4;
            float4 bv = *reinterpret_cast<const float4*>(bias + n);
            float4 o;
            o.x = acc[i2 * 4 + i][j2 * 4 + 0] + bv.x;
            o.y = acc[i2 * 4 + i][j2 * 4 + 1] + bv.y;
            o.z = acc[i2 * 4 + i][j2 * 4 + 2] + bv.z;
            o.w = acc[i2 * 4 + i][j2 * 4 + 3] + bv.w;
            *reinterpret_cast<float4*>(C + (size_t)m * N + n) = o;
        }
    }
}

// ------------------ Wr transpose: WrT[(u*4+g)][k] = Wr[k][g*256+u] ------------------
__global__ void transpose_wr(const float* __restrict__ Wr) {
    int col = blockIdx.x, k = threadIdx.x;
    int u = col & 255, g = col >> 8;
    g_WrT[(u * 4 + g) * 256 + k] = Wr[k * 1024 + col];
}

// ------------------ persistent LSTM: 128 blocks x 128 threads, 2 units/block ------------------
// All 64 timesteps in one launch. Weights in smem for the whole run; cell state in a
// register; h exchanged through compact double buffer + software grid barrier.
// Barrier: one atomicAdd arrival per block; waiters poll a VOLATILE LOAD of the
// generation word (never atomics -> no LTS atomic-ALU serialization).
__global__ void __launch_bounds__(128) lstm_persistent() {
    __shared__ float ws[8][264];   // row = g*2 + usel; pair stride 264 -> 8-bank offset
    int tid = threadIdx.x;
    int usel = tid & 1, b = tid >> 1;
    int u0 = blockIdx.x * 2;
    int u = u0 + usel;

    // load this block's 8 weight rows (2 units x 4 gates x 256) once
    for (int i = tid; i < 2048; i += 128) {
        int row = i >> 8, k = i & 255;
        int uu = row >> 2, g = row & 3;
        ws[g * 2 + uu][k] = g_WrT[((u0 + uu) * 4 + g) * 256 + k];
    }
    __syncthreads();

    const float4* w0 = reinterpret_cast<const float4*>(&ws[0 * 2 + usel][0]);
    const float4* w1 = reinterpret_cast<const float4*>(&ws[1 * 2 + usel][0]);
    const float4* w2 = reinterpret_cast<const float4*>(&ws[2 * 2 + usel][0]);
    const float4* w3 = reinterpret_cast<const float4*>(&ws[3 * 2 + usel][0]);

    float c = 0.f;
    unsigned gen = 0;

    // preload step-0 gate x-parts
    size_t grow0 = (size_t)(b * 64) * 1024 + u;
    float a0 = g_G[grow0 + 0];
    float a1 = g_G[grow0 + 256];
    float a2 = g_G[grow0 + 512];
    float a3 = g_G[grow0 + 768];

    for (int t = 0; t < 64; t++) {
        if (t > 0) {
            const float4* h4 = reinterpret_cast<const float4*>(g_Hb[(t - 1) & 1] + b * 256);
            #pragma unroll 4
            for (int k4 = 0; k4 < 64; k4++) {
                float4 hv = __ldcg(h4 + k4);      // L2 read (coherence point)
                float4 v0 = w0[k4], v1 = w1[k4], v2 = w2[k4], v3 = w3[k4];
                a0 += hv.x * v0.x + hv.y * v0.y + hv.z * v0.z + hv.w * v0.w;
                a1 += hv.x * v1.x + hv.y * v1.y + hv.z * v1.z + hv.w * v1.w;
                a2 += hv.x * v2.x + hv.y * v2.y + hv.z * v2.z + hv.w * v2.w;
                a3 += hv.x * v3.x + hv.y * v3.y + hv.z * v3.z + hv.w * v3.w;
            }
        }
        float cn = sigm(a1) * c + sigm(a0) * tanhf(a2);
        float hn = sigm(a3) * tanhf(cn);
        c = cn;
        g_Hb[t & 1][b * 256 + u] = hn;
        g_HS[(size_t)(b * 64 + t) * 256 + u] = hn;

        if (t < 63) {
            // prefetch next step's gate x-parts (independent of h) before waiting
            size_t grow = (size_t)(b * 64 + t + 1) * 1024 + u;
            float n0v = g_G[grow + 0];
            float n1v = g_G[grow + 256];
            float n2v = g_G[grow + 512];
            float n3v = g_G[grow + 768];

            __threadfence();              // release: h store visible before arrival
            __syncthreads();
            if (tid == 0) {
                unsigned target = gen + 1;
                if (atomicAdd(&g_bar_cnt, 1u) == 127u) {
                    g_bar_cnt = 0u;                       // reset BEFORE release;
                    __threadfence();                      // nobody re-arrives until release seen
                    atomicExch(&g_bar_gen, target);       // publish
                } else {
                    volatile unsigned* gp = &g_bar_gen;   // LOAD polling (no atomic contention)
                    while (*gp < target) __nanosleep(64);
                }
            }
            __syncthreads();
            gen++;

            a0 = n0v; a1 = n1v; a2 = n2v; a3 = n3v;
        }
    }
}

// ------------------ small heads: pir softmax/entropy + vpred (one block/row) ------------------
__global__ void __launch_bounds__(64) heads_kernel(
    const float* __restrict__ pir_W, const float* __restrict__ pir_b,
    const float* __restrict__ v_W,   const float* __restrict__ v_b,
    const int* __restrict__ a_taken)
{
    __shared__ float hrow[256];
    __shared__ float lg[40];
    int r = blockIdx.x, tid = threadIdx.x;
    reinterpret_cast<float4*>(hrow)[tid] =
        reinterpret_cast<const float4*>(g_HS + (size_t)r * 256)[tid];
    __syncthreads();
    if (tid < 36) {
        float acc = pir_b[tid];
        for (int k = 0; k < 256; k++) acc = fmaf(hrow[k], pir_W[k * 36 + tid], acc);
        lg[tid] = acc;
    } else if (tid == 36) {
        float acc = v_b[0];
        for (int k = 0; k < 256; k++) acc = fmaf(hrow[k], v_W[k], acc);
        g_V[r] = acc;
    }
    __syncthreads();
    if (tid == 0) {
        float mx = -1e30f;
        for (int j = 0; j < 36; j++) mx = fmaxf(mx, lg[j]);
        float den = 0.f, s2 = 0.f;
        for (int j = 0; j < 36; j++) {
            float l = lg[j] - mx;
            float e = expf(l);
            den += e; s2 += e * l;
        }
        double ent = log((double)den) - (double)s2 / (double)den;  // -sum p log p
        atomicAdd(&g_acc[0], ent);
        if ((r & 1) == 0) {
            int a = a_taken[r];
            g_P[r] = expf(lg[a] - mx) / den;
        }
    }
}

// ------------------ pim: masked softmax + entropy, one block/row over logits ------------------
__global__ void __launch_bounds__(256) pim_kernel(
    const int* __restrict__ mask, const int* __restrict__ a_taken)
{
    __shared__ float red[256];
    __shared__ float red2[256];
    int r = blockIdx.x, tid = threadIdx.x;
    const float* __restrict__ L = g_L + (size_t)r * NPIM;
    const int* __restrict__ mr = mask + (size_t)r * NPIM;

    // pass 1: full-row max (matches jax softmax stabilization; shift cancels)
    float mx = -1e30f;
    for (int j = tid; j < NPIM; j += 256) mx = fmaxf(mx, L[j]);
    red[tid] = mx; __syncthreads();
    for (int s = 128; s > 0; s >>= 1) {
        if (tid < s) red[tid] = fmaxf(red[tid], red[tid + s]);
        __syncthreads();
    }
    mx = red[0]; __syncthreads();

    // pass 2: s1 = sum e*m, s2 = sum e*m*(l-mx)
    float s1 = 0.f, s2 = 0.f;
    for (int j = tid; j < NPIM; j += 256) {
        float l = L[j] - mx;
        float e = mr[j] ? __expf(l) : 0.f;
        s1 += e; s2 += e * l;
    }
    red[tid] = s1; red2[tid] = s2; __syncthreads();
    for (int s = 128; s > 0; s >>= 1) {
        if (tid < s) { red[tid] += red[tid + s]; red2[tid] += red2[tid + s]; }
        __syncthreads();
    }
    if (tid == 0) {
        float den = red[0];
        // -sum_{m=1} q log q ; masked-out entries (pim_e=1) contribute 0
        double ent = log((double)den) - (double)red2[0] / (double)den;
        atomicAdd(&g_acc[0], ent);
        if (r & 1) {
            int a = a_taken[r];                 // taken action always masked-in
            g_P[r] = __expf(L[a] - mx) / den;
        }
    }
}

// ------------------ vf: faithful (BT,BT) broadcast, one block/row-i ------------------
__global__ void __launch_bounds__(256) vf_kernel(
    const float* __restrict__ ovp, const float* __restrict__ ret)
{
    __shared__ float red[256];
    int i = blockIdx.x, tid = threadIdx.x;
    float v = g_V[i];
    float s = 0.f;
    for (int j = tid; j < BTN; j += 256) {
        float o = ovp[j], rr = ret[j];
        float d = v - o;
        float dc = fminf(fmaxf(d, -0.2f), 0.2f);
        float vpc = o + dc;
        float f1 = (v - rr) * (v - rr);
        float f2 = (vpc - rr) * (vpc - rr);
        s += fmaxf(f1, f2);
    }
    red[tid] = s; __syncthreads();
    for (int st = 128; st > 0; st >>= 1) {
        if (tid < st) red[tid] += red[tid + st];
        __syncthreads();
    }
    if (tid == 0) atomicAdd(&g_acc[1], (double)red[0]);
}

// ------------------ final: gae normalize, pg loss, assemble output ------------------
__global__ void __launch_bounds__(512) final_kernel(
    const float* __restrict__ GAE, const float* __restrict__ lg_old,
    float* __restrict__ out)
{
    __shared__ double rs[512];
    __shared__ double rs2[512];
    __shared__ float stats[2];   // mean, denom
    int tid = threadIdx.x;
    double s = 0.0, ss = 0.0;
    for (int t = tid; t < BTN; t += 512) {
        double g = (double)GAE[t];
        s += g; ss += g * g;
    }
    rs[tid] = s; rs2[tid] = ss; __syncthreads();
    for (int st = 256; st > 0; st >>= 1) {
        if (tid < st) { rs[tid] += rs[tid + st]; rs2[tid] += rs2[tid + st]; }
        __syncthreads();
    }
    if (tid == 0) {
        double mean = rs[0] / BTN;
        double var = rs2[0] / BTN - mean * mean;
        if (var < 0.0) var = 0.0;
        stats[0] = (float)mean;
        stats[1] = (float)(sqrt(var) + 1e-8);
    }
    __syncthreads();
    float mean = stats[0], denom = stats[1];
    double pg = 0.0;
    for (int t = tid; t < BTN; t += 512) {
        float g = (GAE[t] - mean) / denom;
        float p = g_P[t];
        float lgn = logf(p);
        float rt = expf(lgn - lg_old[t]);
        float rtc = fminf(fmaxf(rt, 0.8f), 1.2f);
        float pg1 = -g * rt;
        float pg2 = -g * rtc;
        pg += (double)fmaxf(pg1, pg2);
    }
    rs[tid] = pg; __syncthreads();
    for (int st = 256; st > 0; st >>= 1) {
        if (tid < st) rs[tid] += rs[tid + st];
        __syncthreads();
    }
    if (tid == 0) {
        double pg_loss = rs[0] / BTN;
        double entropy = g_acc[0];
        double vf = 0.5 * g_acc[1] / ((double)BTN * (double)BTN);
        out[0] = (float)(pg_loss - entropy + vf);
        out[1] = (float)pg_loss;
        out[2] = (float)entropy;
        out[3] = (float)vf;
    }
}

// ------------------ launch ------------------
extern "C" void kernel_launch(void* const* d_in, const int* in_sizes, int n_in,
                              void* d_out, int out_size) {
    const float* x       = (const float*)d_in[0];
    const int*   mask    = (const int*)  d_in[1];
    const float* lg_old  = (const float*)d_in[2];
    const int*   a_taken = (const int*)  d_in[3];
    const float* GAE     = (const float*)d_in[4];
    const float* ovp     = (const float*)d_in[5];
    const float* ret     = (const float*)d_in[6];
    const float* W1 = (const float*)d_in[7];
    const float* b1 = (const float*)d_in[8];
    const float* W2 = (const float*)d_in[9];
    const float* b2 = (const float*)d_in[10];
    const float* W3 = (const float*)d_in[11];
    const float* b3 = (const float*)d_in[12];
    const float* W4 = (const float*)d_in[13];
    const float* b4 = (const float*)d_in[14];
    const float* lstm_k = (const float*)d_in[15];
    const float* lstm_r = (const float*)d_in[16];
    const float* lstm_b = (const float*)d_in[17];
    const float* pir_W  = (const float*)d_in[18];
    const float* pir_b  = (const float*)d_in[19];
    const float* pim_W  = (const float*)d_in[20];
    const float* pim_b  = (const float*)d_in[21];
    const float* v_W    = (const float*)d_in[22];
    const float* v_b    = (const float*)d_in[23];
    float* out = (float*)d_out;

    float *pF, *pG, *pHS, *pL;
    cudaGetSymbolAddress((void**)&pF,  g_F);
    cudaGetSymbolAddress((void**)&pG,  g_G);
    cudaGetSymbolAddress((void**)&pHS, g_HS);
    cudaGetSymbolAddress((void**)&pL,  g_L);

    init_kernel<<<1, 256>>>();
    conv_kernel<<<BTN, 128>>>(x, W1, b1, W2, b2, W3, b3, W4, b4);
    transpose_wr<<<1024, 256>>>(lstm_r);

    // G = F @ lstm_k + lstm_b   (4096 x 1024 x 256)
    {
        dim3 grid(1024 / 128, BTN / 128);
        gemm_bias<<<grid, 256>>>(pF, lstm_k, lstm_b, pG, BTN, 1024, 256);
    }

    // all 64 timesteps in one persistent launch
    lstm_persistent<<<128, 128>>>();

    // pim logits = HS @ pim_W + pim_b   (4096 x 4096 x 256)
    {
        dim3 grid(NPIM / 128, BTN / 128);
        gemm_bias<<<grid, 256>>>(pHS, pim_W, pim_b, pL, BTN, NPIM, 256);
    }
    heads_kernel<<<BTN, 64>>>(pir_W, pir_b, v_W, v_b, a_taken);
    pim_kernel<<<BTN, 256>>>(mask, a_taken);
    vf_kernel<<<BTN, 256>>>(ovp, ret);
    final_kernel<<<1, 512>>>(GAE, lg_old, out);
}

// round 14
// speedup vs baseline: 1.6161x; 1.2454x over previous
#include <cuda_runtime.h>
#include <math.h>
#include <stdint.h>

#define BTN 4096          // B*T
#define HN 256            // hidden
#define NPIM 4096

// ------------------ scratch (device globals; no allocation allowed) ------------------
__device__ float  g_F[BTN * 256];          // conv features
__device__ float  g_G[BTN * 1024];         // x@Wk + b (gate x-parts)
__device__ float  g_HS[BTN * 256];         // all lstm hidden states, row=(b*64+t)
__device__ float  g_Hb[2][64 * 256];       // compact double-buffered h (L2-hot)
__device__ float  g_WrT[1024 * 256];       // Wr transposed: [(u*4+gate)][k]
__device__ float  g_L[(size_t)BTN * NPIM]; // pim logits (64MB)
__device__ float  g_P[BTN];                // chosen-action prob per row
__device__ float  g_V[BTN];                // vpred (incl bias)
__device__ double g_acc[2];                // [0]=entropy sum, [1]=vf sum
__device__ unsigned g_bar_cnt;             // grid barrier counter
__device__ unsigned g_bar_gen;             // grid barrier generation

__device__ __forceinline__ float lrelu(float v) { return v > 0.f ? v : 0.2f * v; }
__device__ __forceinline__ float sigm(float v)  { return 1.f / (1.f + expf(-v)); }

// ------------------ init ------------------
__global__ void init_kernel() {
    int i = blockIdx.x * 256 + threadIdx.x;
    if (i < 2) g_acc[i] = 0.0;
    if (i == 2) { g_bar_cnt = 0u; g_bar_gen = 0u; }
}

// ------------------ fused conv stack: one sample per block, 128 threads ------------------
__global__ void __launch_bounds__(128) conv_kernel(
    const float* __restrict__ X,
    const float* __restrict__ W1, const float* __restrict__ b1,
    const float* __restrict__ W2, const float* __restrict__ b2,
    const float* __restrict__ W3, const float* __restrict__ b3,
    const float* __restrict__ W4, const float* __restrict__ b4)
{
    __shared__ float xin[832];   // 13x8x8
    __shared__ float a1[384];    // 6x4x16
    __shared__ float a2[480];    // 5x3x32
    __shared__ float a3[128];    // 2x1x64
    int s = blockIdx.x, tid = threadIdx.x;

    for (int i = tid; i < 832; i += 128) xin[i] = X[(size_t)s * 832 + i];
    __syncthreads();

    // conv1: 2x2 s2 -> (6,4,16)
    if (tid < 96) {
        int cg = tid & 3, xo = (tid >> 2) & 3, yo = tid >> 4;
        float4 acc = *reinterpret_cast<const float4*>(b1 + cg * 4);
        #pragma unroll
        for (int ky = 0; ky < 2; ky++)
        #pragma unroll
        for (int kx = 0; kx < 2; kx++)
        #pragma unroll
        for (int ci = 0; ci < 8; ci++) {
            float v = xin[((2 * yo + ky) * 8 + 2 * xo + kx) * 8 + ci];
            float4 w = *reinterpret_cast<const float4*>(W1 + ((ky * 2 + kx) * 8 + ci) * 16 + cg * 4);
            acc.x = fmaf(v, w.x, acc.x); acc.y = fmaf(v, w.y, acc.y);
            acc.z = fmaf(v, w.z, acc.z); acc.w = fmaf(v, w.w, acc.w);
        }
        int base = (yo * 4 + xo) * 16 + cg * 4;
        a1[base + 0] = lrelu(acc.x); a1[base + 1] = lrelu(acc.y);
        a1[base + 2] = lrelu(acc.z); a1[base + 3] = lrelu(acc.w);
    }
    __syncthreads();

    // conv2: 2x2 s1 -> (5,3,32)
    if (tid < 120) {
        int cg = tid & 7, xo = (tid >> 3) % 3, yo = tid / 24;
        float4 acc = *reinterpret_cast<const float4*>(b2 + cg * 4);
        #pragma unroll
        for (int ky = 0; ky < 2; ky++)
        #pragma unroll
        for (int kx = 0; kx < 2; kx++)
        #pragma unroll
        for (int ci = 0; ci < 16; ci++) {
            float v = a1[((yo + ky) * 4 + xo + kx) * 16 + ci];
            float4 w = *reinterpret_cast<const float4*>(W2 + ((ky * 2 + kx) * 16 + ci) * 32 + cg * 4);
            acc.x = fmaf(v, w.x, acc.x); acc.y = fmaf(v, w.y, acc.y);
            acc.z = fmaf(v, w.z, acc.z); acc.w = fmaf(v, w.w, acc.w);
        }
        int base = (yo * 3 + xo) * 32 + cg * 4;
        a2[base + 0] = lrelu(acc.x); a2[base + 1] = lrelu(acc.y);
        a2[base + 2] = lrelu(acc.z); a2[base + 3] = lrelu(acc.w);
    }
    __syncthreads();

    // conv3: 2x2 s2 -> (2,1,64)
    {
        int yo = tid >> 6, co = tid & 63;
        float acc = b3[co];
        #pragma unroll
        for (int ky = 0; ky < 2; ky++)
        #pragma unroll
        for (int kx = 0; kx < 2; kx++)
        for (int ci = 0; ci < 32; ci++) {
            acc = fmaf(a2[((2 * yo + ky) * 3 + kx) * 32 + ci],
                       W3[((ky * 2 + kx) * 32 + ci) * 64 + co], acc);
        }
        a3[yo * 64 + co] = lrelu(acc);
    }
    __syncthreads();

    // conv4: 1x1 -> (2,1,128); feature j = co*2 + y (keras channels_first flatten)
    #pragma unroll
    for (int rep = 0; rep < 2; rep++) {
        int idx = tid + rep * 128;
        int yo = idx >> 7, co = idx & 127;
        float acc = b4[co];
        for (int ci = 0; ci < 64; ci++)
            acc = fmaf(a3[yo * 64 + ci], W4[ci * 128 + co], acc);
        g_F[(size_t)s * 256 + co * 2 + yo] = lrelu(acc);
    }
}

// ------------------ tiled fp32 GEMM with register-prefetch double buffering ------------------
// C[MxN] = A[MxK] @ W[KxN] + bias. BM=BN=128, BK=8, 256 threads, 8x8 per thread.
__global__ void __launch_bounds__(256, 2) gemm_bias(
    const float* __restrict__ A, const float* __restrict__ W,
    const float* __restrict__ bias, float* __restrict__ C,
    int M, int N, int K)
{
    __shared__ float As[8][128];
    __shared__ float Ws[8][128];
    int m0 = blockIdx.y * 128, n0 = blockIdx.x * 128;
    int tid = threadIdx.x;
    int tx = tid & 15, ty = tid >> 4;
    int lm = tid >> 1, lkq = (tid & 1) * 4;   // A loader
    int lk = tid >> 5, lj = (tid & 31) * 4;   // W loader

    const float* Aptr = A + (size_t)(m0 + lm) * K + lkq;
    const float* Wptr = W + (size_t)lk * N + n0 + lj;

    float acc[8][8];
    #pragma unroll
    for (int i = 0; i < 8; i++)
        #pragma unroll
        for (int j = 0; j < 8; j++) acc[i][j] = 0.f;

    float4 av = *reinterpret_cast<const float4*>(Aptr);
    float4 wv = *reinterpret_cast<const float4*>(Wptr);

    for (int k0 = 0; k0 < K; k0 += 8) {
        As[lkq + 0][lm] = av.x; As[lkq + 1][lm] = av.y;
        As[lkq + 2][lm] = av.z; As[lkq + 3][lm] = av.w;
        *reinterpret_cast<float4*>(&Ws[lk][lj]) = wv;
        __syncthreads();

        if (k0 + 8 < K) {   // prefetch next tile while computing this one
            av = *reinterpret_cast<const float4*>(Aptr + k0 + 8);
            wv = *reinterpret_cast<const float4*>(Wptr + (size_t)(k0 + 8) * N);
        }

        #pragma unroll
        for (int kk = 0; kk < 8; kk++) {
            float4 a0 = *reinterpret_cast<float4*>(&As[kk][ty * 4]);
            float4 a1 = *reinterpret_cast<float4*>(&As[kk][64 + ty * 4]);
            float4 b0 = *reinterpret_cast<float4*>(&Ws[kk][tx * 4]);
            float4 b1 = *reinterpret_cast<float4*>(&Ws[kk][64 + tx * 4]);
            float ar[8] = {a0.x, a0.y, a0.z, a0.w, a1.x, a1.y, a1.z, a1.w};
            float br[8] = {b0.x, b0.y, b0.z, b0.w, b1.x, b1.y, b1.z, b1.w};
            #pragma unroll
            for (int i = 0; i < 8; i++)
                #pragma unroll
                for (int j = 0; j < 8; j++)
                    acc[i][j] = fmaf(ar[i], br[j], acc[i][j]);
        }
        __syncthreads();
    }
    #pragma unroll
    for (int i2 = 0; i2 < 2; i2++)
    #pragma unroll
    for (int i = 0; i < 4; i++) {
        int m = m0 + i2 * 64 + ty * 4 + i;
        #pragma unroll
        for (int j2 = 0; j2 < 2; j2++) {
            int n = n0 + j2 * 64 + tx * 4;
            float4 bv = *reinterpret_cast<const float4*>(bias + n);
            float4 o;
            o.x = acc[i2 * 4 + i][j2 * 4 + 0] + bv.x;
            o.y = acc[i2 * 4 + i][j2 * 4 + 1] + bv.y;
            o.z = acc[i2 * 4 + i][j2 * 4 + 2] + bv.z;
            o.w = acc[i2 * 4 + i][j2 * 4 + 3] + bv.w;
            *reinterpret_cast<float4*>(C + (size_t)m * N + n) = o;
        }
    }
}

// ------------------ Wr transpose: WrT[(u*4+g)][k] = Wr[k][g*256+u] ------------------
__global__ void transpose_wr(const float* __restrict__ Wr) {
    int col = blockIdx.x, k = threadIdx.x;
    int u = col & 255, g = col >> 8;
    g_WrT[(u * 4 + g) * 256 + k] = Wr[k * 1024 + col];
}

// ------------------ persistent LSTM: 128 blocks x 128 threads, 2 units/block ------------------
// h is cooperatively STAGED INTO SHARED MEMORY each step (coalesced, MLP=32), so the
// FMA inner loop reads smem only. Grid barrier: atomic arrival + volatile-load spin
// (no nanosleep). Dynamic smem: h stage (64 rows x 260 pad) + weights (8 rows x 264).
#define HPAD 260
__global__ void __launch_bounds__(128) lstm_persistent() {
    extern __shared__ float dsm[];
    float* hsm = dsm;                    // 64*260 floats
    float* wsm = dsm + 64 * HPAD;        // 8*264 floats
    int tid = threadIdx.x;
    int usel = tid & 1, b = tid >> 1;
    int u0 = blockIdx.x * 2;
    int u = u0 + usel;

    // load this block's 8 weight rows (2 units x 4 gates x 256) once
    for (int i = tid; i < 2048; i += 128) {
        int row = i >> 8, k = i & 255;
        int uu = row >> 2, g = row & 3;
        wsm[(g * 2 + uu) * 264 + k] = g_WrT[((u0 + uu) * 4 + g) * 256 + k];
    }

    const float4* w0 = reinterpret_cast<const float4*>(&wsm[(0 + usel) * 264]);
    const float4* w1 = reinterpret_cast<const float4*>(&wsm[(2 + usel) * 264]);
    const float4* w2 = reinterpret_cast<const float4*>(&wsm[(4 + usel) * 264]);
    const float4* w3 = reinterpret_cast<const float4*>(&wsm[(6 + usel) * 264]);

    float c = 0.f;
    unsigned gen = 0;

    // preload step-0 gate x-parts
    size_t grow0 = (size_t)(b * 64) * 1024 + u;
    float a0 = g_G[grow0 + 0];
    float a1 = g_G[grow0 + 256];
    float a2 = g_G[grow0 + 512];
    float a3 = g_G[grow0 + 768];
    __syncthreads();   // weights ready

    for (int t = 0; t < 64; t++) {
        if (t > 0) {
            // stage full h(t-1) (64x256) into smem, coalesced, deep MLP
            const float4* src = reinterpret_cast<const float4*>(g_Hb[(t - 1) & 1]);
            #pragma unroll
            for (int j = tid; j < 4096; j += 128) {
                float4 hv = __ldcg(src + j);
                int bb = j >> 6, kq = j & 63;
                *reinterpret_cast<float4*>(&hsm[bb * HPAD + kq * 4]) = hv;
            }
            __syncthreads();

            const float4* h4 = reinterpret_cast<const float4*>(&hsm[b * HPAD]);
            #pragma unroll 8
            for (int k4 = 0; k4 < 64; k4++) {
                float4 hv = h4[k4];
                float4 v0 = w0[k4], v1 = w1[k4], v2 = w2[k4], v3 = w3[k4];
                a0 += hv.x * v0.x + hv.y * v0.y + hv.z * v0.z + hv.w * v0.w;
                a1 += hv.x * v1.x + hv.y * v1.y + hv.z * v1.z + hv.w * v1.w;
                a2 += hv.x * v2.x + hv.y * v2.y + hv.z * v2.z + hv.w * v2.w;
                a3 += hv.x * v3.x + hv.y * v3.y + hv.z * v3.z + hv.w * v3.w;
            }
        }
        float cn = sigm(a1) * c + sigm(a0) * tanhf(a2);
        float hn = sigm(a3) * tanhf(cn);
        c = cn;
        g_Hb[t & 1][b * 256 + u] = hn;
        g_HS[(size_t)(b * 64 + t) * 256 + u] = hn;

        if (t < 63) {
            // prefetch next step's gate x-parts (independent of h) before waiting
            size_t grow = (size_t)(b * 64 + t + 1) * 1024 + u;
            float n0v = g_G[grow + 0];
            float n1v = g_G[grow + 256];
            float n2v = g_G[grow + 512];
            float n3v = g_G[grow + 768];

            __threadfence();              // release: h stores visible before arrival
            __syncthreads();
            if (tid == 0) {
                unsigned target = gen + 1;
                if (atomicAdd(&g_bar_cnt, 1u) == 127u) {
                    g_bar_cnt = 0u;                       // reset BEFORE release
                    __threadfence();
                    atomicExch(&g_bar_gen, target);       // publish
                } else {
                    volatile unsigned* gp = &g_bar_gen;   // tight load-poll, no sleep
                    while (*gp < target) { }
                }
            }
            __syncthreads();
            gen++;

            a0 = n0v; a1 = n1v; a2 = n2v; a3 = n3v;
        }
    }
}

// ------------------ small heads: pir softmax/entropy + vpred (one block/row) ------------------
__global__ void __launch_bounds__(64) heads_kernel(
    const float* __restrict__ pir_W, const float* __restrict__ pir_b,
    const float* __restrict__ v_W,   const float* __restrict__ v_b,
    const int* __restrict__ a_taken)
{
    __shared__ float hrow[256];
    __shared__ float lg[40];
    int r = blockIdx.x, tid = threadIdx.x;
    reinterpret_cast<float4*>(hrow)[tid] =
        reinterpret_cast<const float4*>(g_HS + (size_t)r * 256)[tid];
    __syncthreads();
    if (tid < 36) {
        float acc = pir_b[tid];
        for (int k = 0; k < 256; k++) acc = fmaf(hrow[k], pir_W[k * 36 + tid], acc);
        lg[tid] = acc;
    } else if (tid == 36) {
        float acc = v_b[0];
        for (int k = 0; k < 256; k++) acc = fmaf(hrow[k], v_W[k], acc);
        g_V[r] = acc;
    }
    __syncthreads();
    if (tid == 0) {
        float mx = -1e30f;
        for (int j = 0; j < 36; j++) mx = fmaxf(mx, lg[j]);
        float den = 0.f, s2 = 0.f;
        for (int j = 0; j < 36; j++) {
            float l = lg[j] - mx;
            float e = expf(l);
            den += e; s2 += e * l;
        }
        double ent = log((double)den) - (double)s2 / (double)den;  // -sum p log p
        atomicAdd(&g_acc[0], ent);
        if ((r & 1) == 0) {
            int a = a_taken[r];
            g_P[r] = expf(lg[a] - mx) / den;
        }
    }
}

// ------------------ pim: masked softmax + entropy, one block/row over logits ------------------
__global__ void __launch_bounds__(256) pim_kernel(
    const int* __restrict__ mask, const int* __restrict__ a_taken)
{
    __shared__ float red[256];
    __shared__ float red2[256];
    int r = blockIdx.x, tid = threadIdx.x;
    const float* __restrict__ L = g_L + (size_t)r * NPIM;
    const int* __restrict__ mr = mask + (size_t)r * NPIM;

    // pass 1: full-row max (matches jax softmax stabilization; shift cancels)
    float mx = -1e30f;
    for (int j = tid; j < NPIM; j += 256) mx = fmaxf(mx, L[j]);
    red[tid] = mx; __syncthreads();
    for (int s = 128; s > 0; s >>= 1) {
        if (tid < s) red[tid] = fmaxf(red[tid], red[tid + s]);
        __syncthreads();
    }
    mx = red[0]; __syncthreads();

    // pass 2: s1 = sum e*m, s2 = sum e*m*(l-mx)
    float s1 = 0.f, s2 = 0.f;
    for (int j = tid; j < NPIM; j += 256) {
        float l = L[j] - mx;
        float e = mr[j] ? __expf(l) : 0.f;
        s1 += e; s2 += e * l;
    }
    red[tid] = s1; red2[tid] = s2; __syncthreads();
    for (int s = 128; s > 0; s >>= 1) {
        if (tid < s) { red[tid] += red[tid + s]; red2[tid] += red2[tid + s]; }
        __syncthreads();
    }
    if (tid == 0) {
        float den = red[0];
        // -sum_{m=1} q log q ; masked-out entries (pim_e=1) contribute 0
        double ent = log((double)den) - (double)red2[0] / (double)den;
        atomicAdd(&g_acc[0], ent);
        if (r & 1) {
            int a = a_taken[r];                 // taken action always masked-in
            g_P[r] = __expf(L[a] - mx) / den;
        }
    }
}

// ------------------ vf: faithful (BT,BT) broadcast, one block/row-i ------------------
__global__ void __launch_bounds__(256) vf_kernel(
    const float* __restrict__ ovp, const float* __restrict__ ret)
{
    __shared__ float red[256];
    int i = blockIdx.x, tid = threadIdx.x;
    float v = g_V[i];
    float s = 0.f;
    for (int j = tid; j < BTN; j += 256) {
        float o = ovp[j], rr = ret[j];
        float d = v - o;
        float dc = fminf(fmaxf(d, -0.2f), 0.2f);
        float vpc = o + dc;
        float f1 = (v - rr) * (v - rr);
        float f2 = (vpc - rr) * (vpc - rr);
        s += fmaxf(f1, f2);
    }
    red[tid] = s; __syncthreads();
    for (int st = 128; st > 0; st >>= 1) {
        if (tid < st) red[tid] += red[tid + st];
        __syncthreads();
    }
    if (tid == 0) atomicAdd(&g_acc[1], (double)red[0]);
}

// ------------------ final: gae normalize, pg loss, assemble output ------------------
__global__ void __launch_bounds__(512) final_kernel(
    const float* __restrict__ GAE, const float* __restrict__ lg_old,
    float* __restrict__ out)
{
    __shared__ double rs[512];
    __shared__ double rs2[512];
    __shared__ float stats[2];   // mean, denom
    int tid = threadIdx.x;
    double s = 0.0, ss = 0.0;
    for (int t = tid; t < BTN; t += 512) {
        double g = (double)GAE[t];
        s += g; ss += g * g;
    }
    rs[tid] = s; rs2[tid] = ss; __syncthreads();
    for (int st = 256; st > 0; st >>= 1) {
        if (tid < st) { rs[tid] += rs[tid + st]; rs2[tid] += rs2[tid + st]; }
        __syncthreads();
    }
    if (tid == 0) {
        double mean = rs[0] / BTN;
        double var = rs2[0] / BTN - mean * mean;
        if (var < 0.0) var = 0.0;
        stats[0] = (float)mean;
        stats[1] = (float)(sqrt(var) + 1e-8);
    }
    __syncthreads();
    float mean = stats[0], denom = stats[1];
    double pg = 0.0;
    for (int t = tid; t < BTN; t += 512) {
        float g = (GAE[t] - mean) / denom;
        float p = g_P[t];
        float lgn = logf(p);
        float rt = expf(lgn - lg_old[t]);
        float rtc = fminf(fmaxf(rt, 0.8f), 1.2f);
        float pg1 = -g * rt;
        float pg2 = -g * rtc;
        pg += (double)fmaxf(pg1, pg2);
    }
    rs[tid] = pg; __syncthreads();
    for (int st = 256; st > 0; st >>= 1) {
        if (tid < st) rs[tid] += rs[tid + st];
        __syncthreads();
    }
    if (tid == 0) {
        double pg_loss = rs[0] / BTN;
        double entropy = g_acc[0];
        double vf = 0.5 * g_acc[1] / ((double)BTN * (double)BTN);
        out[0] = (float)(pg_loss - entropy + vf);
        out[1] = (float)pg_loss;
        out[2] = (float)entropy;
        out[3] = (float)vf;
    }
}

// ------------------ launch ------------------
extern "C" void kernel_launch(void* const* d_in, const int* in_sizes, int n_in,
                              void* d_out, int out_size) {
    const float* x       = (const float*)d_in[0];
    const int*   mask    = (const int*)  d_in[1];
    const float* lg_old  = (const float*)d_in[2];
    const int*   a_taken = (const int*)  d_in[3];
    const float* GAE     = (const float*)d_in[4];
    const float* ovp     = (const float*)d_in[5];
    const float* ret     = (const float*)d_in[6];
    const float* W1 = (const float*)d_in[7];
    const float* b1 = (const float*)d_in[8];
    const float* W2 = (const float*)d_in[9];
    const float* b2 = (const float*)d_in[10];
    const float* W3 = (const float*)d_in[11];
    const float* b3 = (const float*)d_in[12];
    const float* W4 = (const float*)d_in[13];
    const float* b4 = (const float*)d_in[14];
    const float* lstm_k = (const float*)d_in[15];
    const float* lstm_r = (const float*)d_in[16];
    const float* lstm_b = (const float*)d_in[17];
    const float* pir_W  = (const float*)d_in[18];
    const float* pir_b  = (const float*)d_in[19];
    const float* pim_W  = (const float*)d_in[20];
    const float* pim_b  = (const float*)d_in[21];
    const float* v_W    = (const float*)d_in[22];
    const float* v_b    = (const float*)d_in[23];
    float* out = (float*)d_out;

    float *pF, *pG, *pHS, *pL;
    cudaGetSymbolAddress((void**)&pF,  g_F);
    cudaGetSymbolAddress((void**)&pG,  g_G);
    cudaGetSymbolAddress((void**)&pHS, g_HS);
    cudaGetSymbolAddress((void**)&pL,  g_L);

    const int lstm_smem = (64 * HPAD + 8 * 264) * (int)sizeof(float);  // 75008 B
    cudaFuncSetAttribute(lstm_persistent,
                         cudaFuncAttributeMaxDynamicSharedMemorySize, lstm_smem);

    init_kernel<<<1, 256>>>();
    conv_kernel<<<BTN, 128>>>(x, W1, b1, W2, b2, W3, b3, W4, b4);
    transpose_wr<<<1024, 256>>>(lstm_r);

    // G = F @ lstm_k + lstm_b   (4096 x 1024 x 256)
    {
        dim3 grid(1024 / 128, BTN / 128);
        gemm_bias<<<grid, 256>>>(pF, lstm_k, lstm_b, pG, BTN, 1024, 256);
    }

    // all 64 timesteps in one persistent launch
    lstm_persistent<<<128, 128, lstm_smem>>>();

    // pim logits = HS @ pim_W + pim_b   (4096 x 4096 x 256)
    {
        dim3 grid(NPIM / 128, BTN / 128);
        gemm_bias<<<grid, 256>>>(pHS, pim_W, pim_b, pL, BTN, NPIM, 256);
    }
    heads_kernel<<<BTN, 64>>>(pir_W, pir_b, v_W, v_b, a_taken);
    pim_kernel<<<BTN, 256>>>(mask, a_taken);
    vf_kernel<<<BTN, 256>>>(ovp, ret);
    final_kernel<<<1, 512>>>(GAE, lg_old, out);
}